// round 2
// baseline (speedup 1.0000x reference)
#include <cuda_runtime.h>
#include <math.h>

// Problem constants
#define B_  2
#define S_  2048
#define DM_ 1024
#define H_  16
#define DH_ 64

// ---------------- scratch (no allocations allowed; use __device__ globals) --
__device__ float g_qkv[B_ * S_ * 3 * DM_];        // [B*S, 3072]
__device__ float g_q[B_ * H_ * S_ * DH_];          // [BH, S, 64] (rope applied)
__device__ float g_k[B_ * H_ * S_ * DH_];
__device__ float g_v[B_ * H_ * S_ * DH_];
__device__ float g_ctx[B_ * S_ * DM_];             // [B*S, 1024]

// ---------------------------------------------------------------------------
// SGEMM: C[M,N] = A[M,K] @ B[N,K]^T + bias[N]
// 64x64 tile, BK=16, 256 threads, 4x4 per thread. Smem stored K-major
// (transposed) so the inner loop uses float4 smem loads.
// M,N multiples of 64; K multiple of 16.
// ---------------------------------------------------------------------------
__global__ void sgemm_nt(const float* __restrict__ A, const float* __restrict__ Bm,
                         const float* __restrict__ bias, float* __restrict__ C,
                         int M, int N, int K)
{
    __shared__ __align__(16) float As[16][68];
    __shared__ __align__(16) float Bs[16][68];

    const int tid = threadIdx.x;
    const int tx = tid & 15, ty = tid >> 4;
    const int ry = ty * 4, cx = tx * 4;
    const int m0 = blockIdx.y * 64, n0 = blockIdx.x * 64;

    const int lrow = tid >> 2;          // 0..63
    const int lk   = (tid & 3) * 4;     // 0,4,8,12

    const float* Ap = A  + (size_t)(m0 + lrow) * K + lk;
    const float* Bp = Bm + (size_t)(n0 + lrow) * K + lk;

    float acc[4][4] = {};

    for (int k0 = 0; k0 < K; k0 += 16) {
        float4 a = *(const float4*)(Ap + k0);
        float4 b = *(const float4*)(Bp + k0);
        __syncthreads();
        As[lk + 0][lrow] = a.x; As[lk + 1][lrow] = a.y;
        As[lk + 2][lrow] = a.z; As[lk + 3][lrow] = a.w;
        Bs[lk + 0][lrow] = b.x; Bs[lk + 1][lrow] = b.y;
        Bs[lk + 2][lrow] = b.z; Bs[lk + 3][lrow] = b.w;
        __syncthreads();

        #pragma unroll
        for (int kk = 0; kk < 16; kk++) {
            float4 av = *(const float4*)&As[kk][ry];
            float4 bv = *(const float4*)&Bs[kk][cx];
            float aa[4] = {av.x, av.y, av.z, av.w};
            float bb[4] = {bv.x, bv.y, bv.z, bv.w};
            #pragma unroll
            for (int i = 0; i < 4; i++)
                #pragma unroll
                for (int j = 0; j < 4; j++)
                    acc[i][j] += aa[i] * bb[j];
        }
    }

    const float4 bb4 = *(const float4*)(bias + n0 + cx);
    #pragma unroll
    for (int i = 0; i < 4; i++) {
        float* Cp = C + (size_t)(m0 + ry + i) * N + n0 + cx;
        float4 o;
        o.x = acc[i][0] + bb4.x;
        o.y = acc[i][1] + bb4.y;
        o.z = acc[i][2] + bb4.z;
        o.w = acc[i][3] + bb4.w;
        *(float4*)Cp = o;
    }
}

// ---------------------------------------------------------------------------
// RoPE + split heads. One thread per (b,s,h,j) with j in [0,32).
// qkv row layout: [3][H][Dh].  Outputs Q/K (rotated) and V as [BH][S][Dh].
// rotate_half pairing: (j, j+32), cos/sin identical for both halves.
// ---------------------------------------------------------------------------
__global__ void rope_split(const float* __restrict__ qkv)
{
    int idx = blockIdx.x * blockDim.x + threadIdx.x;   // < B*S*H*32
    int j = idx & 31;
    int t = idx >> 5;
    int h = t & (H_ - 1); t >>= 4;
    int s = t & (S_ - 1);
    int b = t >> 11;

    const float* src = qkv + (size_t)(b * S_ + s) * (3 * DM_) + h * DH_;

    // inv_freq = 10000^(-j/32) = exp(-j * ln(10000)/32)
    float inv = expf(-(float)j * 0.287823136624f);
    float ang = (float)s * inv;
    float sn, cs;
    sincosf(ang, &sn, &cs);

    float q1 = src[j],            q2 = src[j + 32];
    float k1 = src[DM_ + j],      k2 = src[DM_ + j + 32];
    float v1 = src[2 * DM_ + j],  v2 = src[2 * DM_ + j + 32];

    size_t dst = ((size_t)(b * H_ + h) * S_ + s) * DH_;
    g_q[dst + j]      = q1 * cs - q2 * sn;
    g_q[dst + j + 32] = q2 * cs + q1 * sn;
    g_k[dst + j]      = k1 * cs - k2 * sn;
    g_k[dst + j + 32] = k2 * cs + k1 * sn;
    g_v[dst + j]      = v1;
    g_v[dst + j + 32] = v2;
}

// ---------------------------------------------------------------------------
// Flash attention (fp32, causal). CTA = (64 q-rows) x (one bh).
// 256 threads as 16x16, 4x4 microtiles for both QK^T and PV.
// Smem: Qt (Dh-major, transposed), KPt (K transposed, then reused for P),
//       Vs (row-major). All stride 68 floats for conflict avoidance + f4 align.
// Writes ctx in [B,S,H*Dh] layout for the output projection.
// ---------------------------------------------------------------------------
#define AST 68
__global__ void flash_attn(const float* __restrict__ Qg_, const float* __restrict__ Kg_,
                           const float* __restrict__ Vg_, float* __restrict__ ctx)
{
    extern __shared__ __align__(16) float sm[];
    float* Qt  = sm;                 // [64][68]  Qt[d][row]
    float* KPt = sm + 64 * AST;      // [64][68]  Kt[d][col]  then P[row][col]
    float* Vs  = sm + 2 * 64 * AST;  // [64][68]  Vs[tok][d]

    const int tid = threadIdx.x;
    const int tx = tid & 15, ty = tid >> 4;
    const int ry = ty * 4, cx = tx * 4;
    const int bh = blockIdx.y;
    const int qt = blockIdx.x;
    const int q0 = qt * 64;

    const float* Qg = Qg_ + ((size_t)bh * S_ + q0) * DH_;

    // load Q tile transposed
    #pragma unroll
    for (int it = 0; it < 4; it++) {
        int idx = tid + it * 256;            // 0..1023 float4s
        int r = idx >> 4, c = (idx & 15) * 4;
        float4 v = *(const float4*)(Qg + r * DH_ + c);
        Qt[(c + 0) * AST + r] = v.x;
        Qt[(c + 1) * AST + r] = v.y;
        Qt[(c + 2) * AST + r] = v.z;
        Qt[(c + 3) * AST + r] = v.w;
    }

    float m[4], l[4], acc[4][4];
    #pragma unroll
    for (int i = 0; i < 4; i++) {
        m[i] = -3.0e38f; l[i] = 0.f;
        #pragma unroll
        for (int k = 0; k < 4; k++) acc[i][k] = 0.f;
    }

    for (int jt = 0; jt <= qt; jt++) {
        const int j0 = jt * 64;
        const float* Kg = Kg_ + ((size_t)bh * S_ + j0) * DH_;
        const float* Vg = Vg_ + ((size_t)bh * S_ + j0) * DH_;

        __syncthreads();   // previous-iter P/V readers done (and Qt visible on jt==0)
        #pragma unroll
        for (int it = 0; it < 4; it++) {
            int idx = tid + it * 256;
            int r = idx >> 4, c = (idx & 15) * 4;
            float4 kv = *(const float4*)(Kg + r * DH_ + c);
            KPt[(c + 0) * AST + r] = kv.x;
            KPt[(c + 1) * AST + r] = kv.y;
            KPt[(c + 2) * AST + r] = kv.z;
            KPt[(c + 3) * AST + r] = kv.w;
            float4 vv = *(const float4*)(Vg + r * DH_ + c);
            *(float4*)&Vs[r * AST + c] = vv;
        }
        __syncthreads();

        // S = Q @ K^T
        float Sv[4][4] = {};
        #pragma unroll 8
        for (int d = 0; d < 64; d++) {
            float4 qv = *(const float4*)&Qt[d * AST + ry];
            float4 kv = *(const float4*)&KPt[d * AST + cx];
            float qa[4] = {qv.x, qv.y, qv.z, qv.w};
            float ka[4] = {kv.x, kv.y, kv.z, kv.w};
            #pragma unroll
            for (int i = 0; i < 4; i++)
                #pragma unroll
                for (int k = 0; k < 4; k++)
                    Sv[i][k] += qa[i] * ka[k];
        }

        const bool last = (jt == qt);
        #pragma unroll
        for (int i = 0; i < 4; i++)
            #pragma unroll
            for (int k = 0; k < 4; k++) {
                Sv[i][k] *= 0.125f;   // 1/sqrt(64)
                if (last && (cx + k > ry + i)) Sv[i][k] = -1.0e30f;
            }

        // online softmax update (rows are shared by the 16-lane tx-group)
        #pragma unroll
        for (int i = 0; i < 4; i++) {
            float tm = fmaxf(fmaxf(Sv[i][0], Sv[i][1]), fmaxf(Sv[i][2], Sv[i][3]));
            #pragma unroll
            for (int off = 8; off; off >>= 1)
                tm = fmaxf(tm, __shfl_xor_sync(0xffffffffu, tm, off));
            float mn  = fmaxf(m[i], tm);
            float fac = expf(m[i] - mn);
            float rs = 0.f;
            #pragma unroll
            for (int k = 0; k < 4; k++) {
                float p = expf(Sv[i][k] - mn);
                Sv[i][k] = p;
                rs += p;
            }
            #pragma unroll
            for (int off = 8; off; off >>= 1)
                rs += __shfl_xor_sync(0xffffffffu, rs, off);
            l[i] = l[i] * fac + rs;
            m[i] = mn;
            #pragma unroll
            for (int k = 0; k < 4; k++) acc[i][k] *= fac;
        }

        __syncthreads();   // done reading KPt as K
        #pragma unroll
        for (int i = 0; i < 4; i++)
            #pragma unroll
            for (int k = 0; k < 4; k++)
                KPt[(ry + i) * AST + cx + k] = Sv[i][k];
        __syncthreads();

        // acc += P @ V
        #pragma unroll 8
        for (int c = 0; c < 64; c++) {
            float4 vv = *(const float4*)&Vs[c * AST + cx];
            float va[4] = {vv.x, vv.y, vv.z, vv.w};
            float pr[4];
            #pragma unroll
            for (int i = 0; i < 4; i++) pr[i] = KPt[(ry + i) * AST + c];
            #pragma unroll
            for (int i = 0; i < 4; i++)
                #pragma unroll
                for (int k = 0; k < 4; k++)
                    acc[i][k] += pr[i] * va[k];
        }
    }

    const int b = bh >> 4, h = bh & 15;
    #pragma unroll
    for (int i = 0; i < 4; i++) {
        float invl = 1.0f / l[i];
        float* op = ctx + (size_t)(b * S_ + q0 + ry + i) * DM_ + h * DH_ + cx;
        float4 o;
        o.x = acc[i][0] * invl;
        o.y = acc[i][1] * invl;
        o.z = acc[i][2] * invl;
        o.w = acc[i][3] * invl;
        *(float4*)op = o;
    }
}

// ---------------------------------------------------------------------------
extern "C" void kernel_launch(void* const* d_in, const int* in_sizes, int n_in,
                              void* d_out, int out_size)
{
    const float* x      = (const float*)d_in[0];   // [2,2048,1024]
    const float* qkv_w  = (const float*)d_in[1];   // [3072,1024]
    const float* qkv_b  = (const float*)d_in[2];   // [3072]
    const float* proj_w = (const float*)d_in[3];   // [1024,1024]
    const float* proj_b = (const float*)d_in[4];   // [1024]
    float* out = (float*)d_out;                    // [2,2048,1024]

    float *qkv_s, *q_s, *k_s, *v_s, *ctx_s;
    cudaGetSymbolAddress((void**)&qkv_s, g_qkv);
    cudaGetSymbolAddress((void**)&q_s,   g_q);
    cudaGetSymbolAddress((void**)&k_s,   g_k);
    cudaGetSymbolAddress((void**)&v_s,   g_v);
    cudaGetSymbolAddress((void**)&ctx_s, g_ctx);

    // 1) QKV projection: [4096,1024] @ [3072,1024]^T
    {
        dim3 grid(3 * DM_ / 64, B_ * S_ / 64);
        sgemm_nt<<<grid, 256>>>(x, qkv_w, qkv_b, qkv_s, B_ * S_, 3 * DM_, DM_);
    }

    // 2) RoPE + head split
    {
        int total = B_ * S_ * H_ * 32;
        rope_split<<<total / 256, 256>>>(qkv_s);
    }

    // 3) Causal flash attention
    {
        const int smem = 3 * 64 * AST * sizeof(float);  // 52224 B
        cudaFuncSetAttribute(flash_attn, cudaFuncAttributeMaxDynamicSharedMemorySize, smem);
        dim3 grid(S_ / 64, B_ * H_);
        flash_attn<<<grid, 256, smem>>>(q_s, k_s, v_s, ctx_s);
    }

    // 4) Output projection: [4096,1024] @ [1024,1024]^T
    {
        dim3 grid(DM_ / 64, B_ * S_ / 64);
        sgemm_nt<<<grid, 256>>>(ctx_s, proj_w, proj_b, out, B_ * S_, DM_, DM_);
    }
}

// round 5
// speedup vs baseline: 1.4206x; 1.4206x over previous
#include <cuda_runtime.h>
#include <cstdint>
#include <math.h>

// Problem constants
#define B_  2
#define S_  2048
#define DM_ 1024
#define H_  16
#define DH_ 64

// ---------------- scratch (no allocations allowed; use __device__ globals) --
__device__ float g_qkv[B_ * S_ * 3 * DM_];        // [B*S, 3072]
__device__ float g_q[B_ * H_ * S_ * DH_];          // [BH, S, 64] (rope applied)
__device__ float g_k[B_ * H_ * S_ * DH_];
__device__ float g_v[B_ * H_ * S_ * DH_];
__device__ float g_ctx[B_ * S_ * DM_];             // [B*S, 1024]

// ---------------------------------------------------------------------------
// tf32 helpers (warp-level mma.sync — tcgen05 is NOT available: the harness
// PTX targets compute_103 without the 'a' suffix).
// ---------------------------------------------------------------------------
__device__ __forceinline__ uint32_t f2tf32(float x) {
    uint32_t r;
    asm("cvt.rna.tf32.f32 %0, %1;" : "=r"(r) : "f"(x));
    return r;
}

__device__ __forceinline__ void mma_tf32(float& c0, float& c1, float& c2, float& c3,
                                         uint32_t a0, uint32_t a1, uint32_t a2, uint32_t a3,
                                         uint32_t b0, uint32_t b1) {
    asm volatile(
        "mma.sync.aligned.m16n8k8.row.col.f32.tf32.tf32.f32 "
        "{%0,%1,%2,%3}, {%4,%5,%6,%7}, {%8,%9}, {%0,%1,%2,%3};"
        : "+f"(c0), "+f"(c1), "+f"(c2), "+f"(c3)
        : "r"(a0), "r"(a1), "r"(a2), "r"(a3), "r"(b0), "r"(b1));
}

// ---------------------------------------------------------------------------
// tf32 tensor-core GEMM: C[M,N] = A[M,K] @ B[N,K]^T + bias[N]
// CTA tile 128x128, 256 threads = 8 warps (2 x 4), warp tile 64x32.
// K-chunks of 32, double-buffered smem (stride 36: conflict-free frag loads),
// register prefetch of the next chunk. Values stored in smem already tf32-
// rounded (cvt.rna) so products are unbiased. M,N %128==0, K %32==0.
// ---------------------------------------------------------------------------
#define GST 36
#define GEMM_SMEM (4 * 128 * GST * 4)   // A[2] + B[2] buffers, 73728 B

__global__ void __launch_bounds__(256, 1)
gemm_tf32(const float* __restrict__ A, const float* __restrict__ Bw,
          const float* __restrict__ bias, float* __restrict__ C,
          int M, int N, int K)
{
    extern __shared__ __align__(16) float sm[];
    float* As[2] = { sm,                sm + 128 * GST };
    float* Bs[2] = { sm + 2 * 128 * GST, sm + 3 * 128 * GST };

    const int tid  = threadIdx.x;
    const int wid  = tid >> 5, lane = tid & 31;
    const int wm   = (wid >> 2) * 64;         // warp row offset (0,64)
    const int wn   = (wid & 3) * 32;          // warp col offset (0..96)
    const int lr   = lane >> 2;               // 0..7
    const int lc   = lane & 3;                // 0..3
    const int m0 = blockIdx.y * 128, n0 = blockIdx.x * 128;
    const int NK = K >> 5;

    // gmem slice: 4 float4 per tile per thread
    const int r0 = tid >> 3;                  // 0..31 (+32 per it)
    const int c4 = (tid & 7) * 4;             // 0..28
    const float* Ab = A  + (size_t)(m0 + r0) * K + c4;
    const float* Bb = Bw + (size_t)(n0 + r0) * K + c4;

    float acc[4][4][4];
    #pragma unroll
    for (int t = 0; t < 4; t++)
        #pragma unroll
        for (int j = 0; j < 4; j++)
            #pragma unroll
            for (int r = 0; r < 4; r++) acc[t][j][r] = 0.f;

    // prologue: chunk 0 -> buffer 0 (tf32-rounded)
    #pragma unroll
    for (int it = 0; it < 4; it++) {
        int r = r0 + it * 32;
        float4 a = *(const float4*)(Ab + (size_t)(it * 32) * K);
        float4 b = *(const float4*)(Bb + (size_t)(it * 32) * K);
        float* ap = As[0] + r * GST + c4;
        ap[0] = __uint_as_float(f2tf32(a.x)); ap[1] = __uint_as_float(f2tf32(a.y));
        ap[2] = __uint_as_float(f2tf32(a.z)); ap[3] = __uint_as_float(f2tf32(a.w));
        float* bp = Bs[0] + r * GST + c4;
        bp[0] = __uint_as_float(f2tf32(b.x)); bp[1] = __uint_as_float(f2tf32(b.y));
        bp[2] = __uint_as_float(f2tf32(b.z)); bp[3] = __uint_as_float(f2tf32(b.w));
    }
    __syncthreads();

    for (int kc = 0; kc < NK; kc++) {
        const int p = kc & 1;

        float4 ra[4], rb[4];
        if (kc + 1 < NK) {
            const int ko = (kc + 1) * 32;
            #pragma unroll
            for (int it = 0; it < 4; it++) {
                ra[it] = *(const float4*)(Ab + (size_t)(it * 32) * K + ko);
                rb[it] = *(const float4*)(Bb + (size_t)(it * 32) * K + ko);
            }
        }

        const float* Ap = As[p];
        const float* Bp = Bs[p];
        #pragma unroll
        for (int ks = 0; ks < 4; ks++) {
            const int kb = ks * 8;
            uint32_t af[4][4];
            #pragma unroll
            for (int t = 0; t < 4; t++) {
                const float* base = Ap + (wm + t * 16 + lr) * GST + kb + lc;
                af[t][0] = __float_as_uint(base[0]);
                af[t][1] = __float_as_uint(base[8 * GST]);
                af[t][2] = __float_as_uint(base[4]);
                af[t][3] = __float_as_uint(base[8 * GST + 4]);
            }
            uint32_t bf[4][2];
            #pragma unroll
            for (int j = 0; j < 4; j++) {
                const float* base = Bp + (wn + j * 8 + lr) * GST + kb + lc;
                bf[j][0] = __float_as_uint(base[0]);
                bf[j][1] = __float_as_uint(base[4]);
            }
            #pragma unroll
            for (int t = 0; t < 4; t++)
                #pragma unroll
                for (int j = 0; j < 4; j++)
                    mma_tf32(acc[t][j][0], acc[t][j][1], acc[t][j][2], acc[t][j][3],
                             af[t][0], af[t][1], af[t][2], af[t][3],
                             bf[j][0], bf[j][1]);
        }

        if (kc + 1 < NK) {
            const int q = p ^ 1;
            #pragma unroll
            for (int it = 0; it < 4; it++) {
                int r = r0 + it * 32;
                float* ap = As[q] + r * GST + c4;
                ap[0] = __uint_as_float(f2tf32(ra[it].x)); ap[1] = __uint_as_float(f2tf32(ra[it].y));
                ap[2] = __uint_as_float(f2tf32(ra[it].z)); ap[3] = __uint_as_float(f2tf32(ra[it].w));
                float* bp = Bs[q] + r * GST + c4;
                bp[0] = __uint_as_float(f2tf32(rb[it].x)); bp[1] = __uint_as_float(f2tf32(rb[it].y));
                bp[2] = __uint_as_float(f2tf32(rb[it].z)); bp[3] = __uint_as_float(f2tf32(rb[it].w));
            }
            __syncthreads();
        }
    }

    // epilogue: fragment layout c0,c1 -> (row, 2*lc), (row, 2*lc+1); c2,c3 -> row+8
    #pragma unroll
    for (int t = 0; t < 4; t++) {
        const int row = m0 + wm + t * 16 + lr;
        #pragma unroll
        for (int j = 0; j < 4; j++) {
            const int col = n0 + wn + j * 8 + 2 * lc;
            const float b0 = bias[col], b1 = bias[col + 1];
            float2 o0 = { acc[t][j][0] + b0, acc[t][j][1] + b1 };
            float2 o1 = { acc[t][j][2] + b0, acc[t][j][3] + b1 };
            *(float2*)(C + (size_t)row * N + col)       = o0;
            *(float2*)(C + (size_t)(row + 8) * N + col) = o1;
        }
    }
}

// ---------------------------------------------------------------------------
// RoPE + split heads. One thread per (b,s,h,j) with j in [0,32).
// ---------------------------------------------------------------------------
__global__ void rope_split(const float* __restrict__ qkv)
{
    int idx = blockIdx.x * blockDim.x + threadIdx.x;   // < B*S*H*32
    int j = idx & 31;
    int t = idx >> 5;
    int h = t & (H_ - 1); t >>= 4;
    int s = t & (S_ - 1);
    int b = t >> 11;

    const float* src = qkv + (size_t)(b * S_ + s) * (3 * DM_) + h * DH_;

    float inv = expf(-(float)j * 0.287823136624f);   // 10000^(-j/32)
    float ang = (float)s * inv;
    float sn, cs;
    sincosf(ang, &sn, &cs);

    float q1 = src[j],            q2 = src[j + 32];
    float k1 = src[DM_ + j],      k2 = src[DM_ + j + 32];
    float v1 = src[2 * DM_ + j],  v2 = src[2 * DM_ + j + 32];

    size_t dst = ((size_t)(b * H_ + h) * S_ + s) * DH_;
    g_q[dst + j]      = q1 * cs - q2 * sn;
    g_q[dst + j + 32] = q2 * cs + q1 * sn;
    g_k[dst + j]      = k1 * cs - k2 * sn;
    g_k[dst + j + 32] = k2 * cs + k1 * sn;
    g_v[dst + j]      = v1;
    g_v[dst + j + 32] = v2;
}

// ---------------------------------------------------------------------------
// Flash attention (fp32, causal), unchanged from R2.
// ---------------------------------------------------------------------------
#define AST 68
__global__ void flash_attn(const float* __restrict__ Qg_, const float* __restrict__ Kg_,
                           const float* __restrict__ Vg_, float* __restrict__ ctx)
{
    extern __shared__ __align__(16) float smf[];
    float* Qt  = smf;
    float* KPt = smf + 64 * AST;
    float* Vs  = smf + 2 * 64 * AST;

    const int tid = threadIdx.x;
    const int tx = tid & 15, ty = tid >> 4;
    const int ry = ty * 4, cx = tx * 4;
    const int bh = blockIdx.y;
    const int qt = blockIdx.x;
    const int q0 = qt * 64;

    const float* Qg = Qg_ + ((size_t)bh * S_ + q0) * DH_;

    #pragma unroll
    for (int it = 0; it < 4; it++) {
        int idx = tid + it * 256;
        int r = idx >> 4, c = (idx & 15) * 4;
        float4 v = *(const float4*)(Qg + r * DH_ + c);
        Qt[(c + 0) * AST + r] = v.x;
        Qt[(c + 1) * AST + r] = v.y;
        Qt[(c + 2) * AST + r] = v.z;
        Qt[(c + 3) * AST + r] = v.w;
    }

    float m[4], l[4], acc[4][4];
    #pragma unroll
    for (int i = 0; i < 4; i++) {
        m[i] = -3.0e38f; l[i] = 0.f;
        #pragma unroll
        for (int k = 0; k < 4; k++) acc[i][k] = 0.f;
    }

    for (int jt = 0; jt <= qt; jt++) {
        const int j0 = jt * 64;
        const float* Kg = Kg_ + ((size_t)bh * S_ + j0) * DH_;
        const float* Vg = Vg_ + ((size_t)bh * S_ + j0) * DH_;

        __syncthreads();
        #pragma unroll
        for (int it = 0; it < 4; it++) {
            int idx = tid + it * 256;
            int r = idx >> 4, c = (idx & 15) * 4;
            float4 kv = *(const float4*)(Kg + r * DH_ + c);
            KPt[(c + 0) * AST + r] = kv.x;
            KPt[(c + 1) * AST + r] = kv.y;
            KPt[(c + 2) * AST + r] = kv.z;
            KPt[(c + 3) * AST + r] = kv.w;
            float4 vv = *(const float4*)(Vg + r * DH_ + c);
            *(float4*)&Vs[r * AST + c] = vv;
        }
        __syncthreads();

        float Sv[4][4] = {};
        #pragma unroll 8
        for (int d = 0; d < 64; d++) {
            float4 qv = *(const float4*)&Qt[d * AST + ry];
            float4 kv = *(const float4*)&KPt[d * AST + cx];
            float qa[4] = {qv.x, qv.y, qv.z, qv.w};
            float ka[4] = {kv.x, kv.y, kv.z, kv.w};
            #pragma unroll
            for (int i = 0; i < 4; i++)
                #pragma unroll
                for (int k = 0; k < 4; k++)
                    Sv[i][k] += qa[i] * ka[k];
        }

        const bool last = (jt == qt);
        #pragma unroll
        for (int i = 0; i < 4; i++)
            #pragma unroll
            for (int k = 0; k < 4; k++) {
                Sv[i][k] *= 0.125f;
                if (last && (cx + k > ry + i)) Sv[i][k] = -1.0e30f;
            }

        #pragma unroll
        for (int i = 0; i < 4; i++) {
            float tm = fmaxf(fmaxf(Sv[i][0], Sv[i][1]), fmaxf(Sv[i][2], Sv[i][3]));
            #pragma unroll
            for (int off = 8; off; off >>= 1)
                tm = fmaxf(tm, __shfl_xor_sync(0xffffffffu, tm, off));
            float mn  = fmaxf(m[i], tm);
            float fac = expf(m[i] - mn);
            float rs = 0.f;
            #pragma unroll
            for (int k = 0; k < 4; k++) {
                float p = expf(Sv[i][k] - mn);
                Sv[i][k] = p;
                rs += p;
            }
            #pragma unroll
            for (int off = 8; off; off >>= 1)
                rs += __shfl_xor_sync(0xffffffffu, rs, off);
            l[i] = l[i] * fac + rs;
            m[i] = mn;
            #pragma unroll
            for (int k = 0; k < 4; k++) acc[i][k] *= fac;
        }

        __syncthreads();
        #pragma unroll
        for (int i = 0; i < 4; i++)
            #pragma unroll
            for (int k = 0; k < 4; k++)
                KPt[(ry + i) * AST + cx + k] = Sv[i][k];
        __syncthreads();

        #pragma unroll 8
        for (int c = 0; c < 64; c++) {
            float4 vv = *(const float4*)&Vs[c * AST + cx];
            float va[4] = {vv.x, vv.y, vv.z, vv.w};
            float pr[4];
            #pragma unroll
            for (int i = 0; i < 4; i++) pr[i] = KPt[(ry + i) * AST + c];
            #pragma unroll
            for (int i = 0; i < 4; i++)
                #pragma unroll
                for (int k = 0; k < 4; k++)
                    acc[i][k] += pr[i] * va[k];
        }
    }

    const int b = bh >> 4, h = bh & 15;
    #pragma unroll
    for (int i = 0; i < 4; i++) {
        float invl = 1.0f / l[i];
        float* op = ctx + (size_t)(b * S_ + q0 + ry + i) * DM_ + h * DH_ + cx;
        float4 o;
        o.x = acc[i][0] * invl;
        o.y = acc[i][1] * invl;
        o.z = acc[i][2] * invl;
        o.w = acc[i][3] * invl;
        *(float4*)op = o;
    }
}

// ---------------------------------------------------------------------------
extern "C" void kernel_launch(void* const* d_in, const int* in_sizes, int n_in,
                              void* d_out, int out_size)
{
    const float* x      = (const float*)d_in[0];   // [2,2048,1024]
    const float* qkv_w  = (const float*)d_in[1];   // [3072,1024]
    const float* qkv_b  = (const float*)d_in[2];   // [3072]
    const float* proj_w = (const float*)d_in[3];   // [1024,1024]
    const float* proj_b = (const float*)d_in[4];   // [1024]
    float* out = (float*)d_out;                    // [2,2048,1024]

    float *qkv_s, *q_s, *k_s, *v_s, *ctx_s;
    cudaGetSymbolAddress((void**)&qkv_s, g_qkv);
    cudaGetSymbolAddress((void**)&q_s,   g_q);
    cudaGetSymbolAddress((void**)&k_s,   g_k);
    cudaGetSymbolAddress((void**)&v_s,   g_v);
    cudaGetSymbolAddress((void**)&ctx_s, g_ctx);

    cudaFuncSetAttribute(gemm_tf32, cudaFuncAttributeMaxDynamicSharedMemorySize, GEMM_SMEM);

    // 1) QKV projection: [4096,1024] @ [3072,1024]^T  (tf32 mma.sync)
    {
        dim3 grid(3 * DM_ / 128, B_ * S_ / 128);
        gemm_tf32<<<grid, 256, GEMM_SMEM>>>(x, qkv_w, qkv_b, qkv_s, B_ * S_, 3 * DM_, DM_);
    }

    // 2) RoPE + head split
    {
        int total = B_ * S_ * H_ * 32;
        rope_split<<<total / 256, 256>>>(qkv_s);
    }

    // 3) Causal flash attention (fp32)
    {
        const int smem = 3 * 64 * AST * sizeof(float);
        cudaFuncSetAttribute(flash_attn, cudaFuncAttributeMaxDynamicSharedMemorySize, smem);
        dim3 grid(S_ / 64, B_ * H_);
        flash_attn<<<grid, 256, smem>>>(q_s, k_s, v_s, ctx_s);
    }

    // 4) Output projection: [4096,1024] @ [1024,1024]^T  (tf32 mma.sync)
    {
        dim3 grid(DM_ / 128, B_ * S_ / 128);
        gemm_tf32<<<grid, 256, GEMM_SMEM>>>(ctx_s, proj_w, proj_b, out, B_ * S_, DM_, DM_);
    }
}

// round 6
// speedup vs baseline: 2.3792x; 1.6748x over previous
#include <cuda_runtime.h>
#include <cstdint>
#include <math.h>

// Problem constants
#define B_  2
#define S_  2048
#define DM_ 1024
#define H_  16
#define DH_ 64

// ---------------- scratch (no allocations allowed; use __device__ globals) --
__device__ float g_qkv[B_ * S_ * 3 * DM_];        // [B*S, 3072]
__device__ float g_q[B_ * H_ * S_ * DH_];          // [BH, S, 64] (rope applied)
__device__ float g_k[B_ * H_ * S_ * DH_];
__device__ float g_v[B_ * H_ * S_ * DH_];
__device__ float g_ctx[B_ * S_ * DM_];             // [B*S, 1024]

// ---------------------------------------------------------------------------
// tf32 helpers (warp-level mma.sync — tcgen05 unavailable: harness targets
// compute_103 without the 'a' suffix).
// ---------------------------------------------------------------------------
__device__ __forceinline__ uint32_t f2tf32(float x) {
    uint32_t r;
    asm("cvt.rna.tf32.f32 %0, %1;" : "=r"(r) : "f"(x));
    return r;
}
__device__ __forceinline__ float rt32(float x) { return __uint_as_float(f2tf32(x)); }

__device__ __forceinline__ void mma_tf32(float& c0, float& c1, float& c2, float& c3,
                                         uint32_t a0, uint32_t a1, uint32_t a2, uint32_t a3,
                                         uint32_t b0, uint32_t b1) {
    asm volatile(
        "mma.sync.aligned.m16n8k8.row.col.f32.tf32.tf32.f32 "
        "{%0,%1,%2,%3}, {%4,%5,%6,%7}, {%8,%9}, {%0,%1,%2,%3};"
        : "+f"(c0), "+f"(c1), "+f"(c2), "+f"(c3)
        : "r"(a0), "r"(a1), "r"(a2), "r"(a3), "r"(b0), "r"(b1));
}

// ---------------------------------------------------------------------------
// tf32 tensor-core GEMM: C[M,N] = A[M,K] @ B[N,K]^T + bias[N]  (as R5)
// ---------------------------------------------------------------------------
#define GST 36
#define GEMM_SMEM (4 * 128 * GST * 4)   // 73728 B

__global__ void __launch_bounds__(256, 1)
gemm_tf32(const float* __restrict__ A, const float* __restrict__ Bw,
          const float* __restrict__ bias, float* __restrict__ C,
          int M, int N, int K)
{
    extern __shared__ __align__(16) float sm[];
    float* As[2] = { sm,                 sm + 128 * GST };
    float* Bs[2] = { sm + 2 * 128 * GST, sm + 3 * 128 * GST };

    const int tid  = threadIdx.x;
    const int wid  = tid >> 5, lane = tid & 31;
    const int wm   = (wid >> 2) * 64;
    const int wn   = (wid & 3) * 32;
    const int lr   = lane >> 2;
    const int lc   = lane & 3;
    const int m0 = blockIdx.y * 128, n0 = blockIdx.x * 128;
    const int NK = K >> 5;

    const int r0 = tid >> 3;
    const int c4 = (tid & 7) * 4;
    const float* Ab = A  + (size_t)(m0 + r0) * K + c4;
    const float* Bb = Bw + (size_t)(n0 + r0) * K + c4;

    float acc[4][4][4];
    #pragma unroll
    for (int t = 0; t < 4; t++)
        #pragma unroll
        for (int j = 0; j < 4; j++)
            #pragma unroll
            for (int r = 0; r < 4; r++) acc[t][j][r] = 0.f;

    #pragma unroll
    for (int it = 0; it < 4; it++) {
        int r = r0 + it * 32;
        float4 a = *(const float4*)(Ab + (size_t)(it * 32) * K);
        float4 b = *(const float4*)(Bb + (size_t)(it * 32) * K);
        float* ap = As[0] + r * GST + c4;
        ap[0] = rt32(a.x); ap[1] = rt32(a.y); ap[2] = rt32(a.z); ap[3] = rt32(a.w);
        float* bp = Bs[0] + r * GST + c4;
        bp[0] = rt32(b.x); bp[1] = rt32(b.y); bp[2] = rt32(b.z); bp[3] = rt32(b.w);
    }
    __syncthreads();

    for (int kc = 0; kc < NK; kc++) {
        const int p = kc & 1;

        float4 ra[4], rb[4];
        if (kc + 1 < NK) {
            const int ko = (kc + 1) * 32;
            #pragma unroll
            for (int it = 0; it < 4; it++) {
                ra[it] = *(const float4*)(Ab + (size_t)(it * 32) * K + ko);
                rb[it] = *(const float4*)(Bb + (size_t)(it * 32) * K + ko);
            }
        }

        const float* Ap = As[p];
        const float* Bp = Bs[p];
        #pragma unroll
        for (int ks = 0; ks < 4; ks++) {
            const int kb = ks * 8;
            uint32_t af[4][4];
            #pragma unroll
            for (int t = 0; t < 4; t++) {
                const float* base = Ap + (wm + t * 16 + lr) * GST + kb + lc;
                af[t][0] = __float_as_uint(base[0]);
                af[t][1] = __float_as_uint(base[8 * GST]);
                af[t][2] = __float_as_uint(base[4]);
                af[t][3] = __float_as_uint(base[8 * GST + 4]);
            }
            uint32_t bf[4][2];
            #pragma unroll
            for (int j = 0; j < 4; j++) {
                const float* base = Bp + (wn + j * 8 + lr) * GST + kb + lc;
                bf[j][0] = __float_as_uint(base[0]);
                bf[j][1] = __float_as_uint(base[4]);
            }
            #pragma unroll
            for (int t = 0; t < 4; t++)
                #pragma unroll
                for (int j = 0; j < 4; j++)
                    mma_tf32(acc[t][j][0], acc[t][j][1], acc[t][j][2], acc[t][j][3],
                             af[t][0], af[t][1], af[t][2], af[t][3],
                             bf[j][0], bf[j][1]);
        }

        if (kc + 1 < NK) {
            const int q = p ^ 1;
            #pragma unroll
            for (int it = 0; it < 4; it++) {
                int r = r0 + it * 32;
                float* ap = As[q] + r * GST + c4;
                ap[0] = rt32(ra[it].x); ap[1] = rt32(ra[it].y);
                ap[2] = rt32(ra[it].z); ap[3] = rt32(ra[it].w);
                float* bp = Bs[q] + r * GST + c4;
                bp[0] = rt32(rb[it].x); bp[1] = rt32(rb[it].y);
                bp[2] = rt32(rb[it].z); bp[3] = rt32(rb[it].w);
            }
            __syncthreads();
        }
    }

    #pragma unroll
    for (int t = 0; t < 4; t++) {
        const int row = m0 + wm + t * 16 + lr;
        #pragma unroll
        for (int j = 0; j < 4; j++) {
            const int col = n0 + wn + j * 8 + 2 * lc;
            const float b0 = bias[col], b1 = bias[col + 1];
            float2 o0 = { acc[t][j][0] + b0, acc[t][j][1] + b1 };
            float2 o1 = { acc[t][j][2] + b0, acc[t][j][3] + b1 };
            *(float2*)(C + (size_t)row * N + col)       = o0;
            *(float2*)(C + (size_t)(row + 8) * N + col) = o1;
        }
    }
}

// ---------------------------------------------------------------------------
// RoPE + split heads (unchanged).
// ---------------------------------------------------------------------------
__global__ void rope_split(const float* __restrict__ qkv)
{
    int idx = blockIdx.x * blockDim.x + threadIdx.x;
    int j = idx & 31;
    int t = idx >> 5;
    int h = t & (H_ - 1); t >>= 4;
    int s = t & (S_ - 1);
    int b = t >> 11;

    const float* src = qkv + (size_t)(b * S_ + s) * (3 * DM_) + h * DH_;

    float inv = expf(-(float)j * 0.287823136624f);
    float ang = (float)s * inv;
    float sn, cs;
    sincosf(ang, &sn, &cs);

    float q1 = src[j],            q2 = src[j + 32];
    float k1 = src[DM_ + j],      k2 = src[DM_ + j + 32];
    float v1 = src[2 * DM_ + j],  v2 = src[2 * DM_ + j + 32];

    size_t dst = ((size_t)(b * H_ + h) * S_ + s) * DH_;
    g_q[dst + j]      = q1 * cs - q2 * sn;
    g_q[dst + j + 32] = q2 * cs + q1 * sn;
    g_k[dst + j]      = k1 * cs - k2 * sn;
    g_k[dst + j + 32] = k2 * cs + k1 * sn;
    g_v[dst + j]      = v1;
    g_v[dst + j + 32] = v2;
}

// ---------------------------------------------------------------------------
// Flash attention on tensor cores (tf32 mma.sync, fp32 accum, causal).
// CTA: 128 q-rows x one bh. 8 warps, 16 q-rows each. KV tiles of 64.
// Q held as A-fragments in registers (pre-scaled by 1/8, tf32-rounded).
// K/V staged in smem (stride 68 -> conflict-free fragment reads),
// register prefetch of the next tile. P goes through per-warp smem slice.
// ---------------------------------------------------------------------------
#define FST 68
#define FLASH_SMEM ((2 * 64 * FST + 128 * FST) * 4)   // 69632 B

__global__ void __launch_bounds__(256, 1)
flash_tc(const float* __restrict__ Qg, const float* __restrict__ Kg,
         const float* __restrict__ Vg, float* __restrict__ ctx)
{
    extern __shared__ __align__(16) float sm[];
    float* Ks = sm;
    float* Vs = sm + 64 * FST;
    float* Ps = sm + 2 * 64 * FST;      // Q staging, then per-warp P slices

    const int tid  = threadIdx.x;
    const int wid  = tid >> 5, lane = tid & 31;
    const int g    = lane >> 2, qd = lane & 3;
    const int wq0  = wid * 16;
    const int bh   = blockIdx.y;
    const int qt   = (gridDim.x - 1) - blockIdx.x;   // longest CTAs first
    const int q0   = qt * 128;

    const float* Qbase = Qg + ((size_t)bh * S_ + q0) * DH_;
    const float* Kbase = Kg + (size_t)bh * S_ * DH_;
    const float* Vbase = Vg + (size_t)bh * S_ * DH_;

    // stage Q (scaled, tf32-rounded) into Ps
    #pragma unroll
    for (int it = 0; it < 8; it++) {
        int idx = tid + it * 256;
        int r = idx >> 4, c = (idx & 15) * 4;
        float4 v = *(const float4*)(Qbase + r * DH_ + c);
        float* p = Ps + r * FST + c;
        p[0] = rt32(v.x * 0.125f); p[1] = rt32(v.y * 0.125f);
        p[2] = rt32(v.z * 0.125f); p[3] = rt32(v.w * 0.125f);
    }
    __syncthreads();

    // Q fragments: 8 k-steps x 4 regs
    uint32_t qf[8][4];
    #pragma unroll
    for (int kb = 0; kb < 8; kb++) {
        const float* b0 = Ps + (wq0 + g) * FST + kb * 8 + qd;
        qf[kb][0] = __float_as_uint(b0[0]);
        qf[kb][1] = __float_as_uint(b0[8 * FST]);
        qf[kb][2] = __float_as_uint(b0[4]);
        qf[kb][3] = __float_as_uint(b0[8 * FST + 4]);
    }
    __syncthreads();

    // prologue: KV tile 0 into smem
    const int r0 = tid >> 4;           // 0..15 (+16 per it)
    const int c4 = (tid & 15) * 4;
    #pragma unroll
    for (int it = 0; it < 4; it++) {
        int r = r0 + it * 16;
        float4 k4 = *(const float4*)(Kbase + r * DH_ + c4);
        float4 v4 = *(const float4*)(Vbase + r * DH_ + c4);
        float* kp = Ks + r * FST + c4;
        kp[0] = rt32(k4.x); kp[1] = rt32(k4.y); kp[2] = rt32(k4.z); kp[3] = rt32(k4.w);
        float* vp = Vs + r * FST + c4;
        vp[0] = rt32(v4.x); vp[1] = rt32(v4.y); vp[2] = rt32(v4.z); vp[3] = rt32(v4.w);
    }
    __syncthreads();

    float m0v = -3.0e38f, m1v = -3.0e38f, l0 = 0.f, l1 = 0.f;
    float oacc[8][4];
    #pragma unroll
    for (int nb = 0; nb < 8; nb++)
        #pragma unroll
        for (int r = 0; r < 4; r++) oacc[nb][r] = 0.f;

    const int rowa = q0 + wq0 + g;
    const int rowb = rowa + 8;
    const int ntiles = q0 / 64 + 2;

    for (int jt = 0; jt < ntiles; jt++) {
        const int j0 = jt * 64;
        const bool more = (jt + 1 < ntiles);

        // prefetch next KV tile into regs
        float4 rk[4], rv[4];
        if (more) {
            const float* Kn = Kbase + (size_t)(j0 + 64) * DH_;
            const float* Vn = Vbase + (size_t)(j0 + 64) * DH_;
            #pragma unroll
            for (int it = 0; it < 4; it++) {
                rk[it] = *(const float4*)(Kn + (r0 + it * 16) * DH_ + c4);
                rv[it] = *(const float4*)(Vn + (r0 + it * 16) * DH_ + c4);
            }
        }

        // S = Q @ K^T   (scaled already)
        float sacc[8][4];
        #pragma unroll
        for (int nb = 0; nb < 8; nb++)
            #pragma unroll
            for (int r = 0; r < 4; r++) sacc[nb][r] = 0.f;

        #pragma unroll
        for (int kb = 0; kb < 8; kb++) {
            #pragma unroll
            for (int nb = 0; nb < 8; nb++) {
                const float* bp = Ks + (nb * 8 + g) * FST + kb * 8 + qd;
                uint32_t b0 = __float_as_uint(bp[0]);
                uint32_t b1 = __float_as_uint(bp[4]);
                mma_tf32(sacc[nb][0], sacc[nb][1], sacc[nb][2], sacc[nb][3],
                         qf[kb][0], qf[kb][1], qf[kb][2], qf[kb][3], b0, b1);
            }
        }

        // causal mask
        if (j0 + 63 > rowa) {
            #pragma unroll
            for (int nb = 0; nb < 8; nb++) {
                int col = j0 + nb * 8 + 2 * qd;
                if (col     > rowa) sacc[nb][0] = -1.0e30f;
                if (col + 1 > rowa) sacc[nb][1] = -1.0e30f;
                if (col     > rowb) sacc[nb][2] = -1.0e30f;
                if (col + 1 > rowb) sacc[nb][3] = -1.0e30f;
            }
        }

        // online softmax
        float t0 = -3.0e38f, t1 = -3.0e38f;
        #pragma unroll
        for (int nb = 0; nb < 8; nb++) {
            t0 = fmaxf(t0, fmaxf(sacc[nb][0], sacc[nb][1]));
            t1 = fmaxf(t1, fmaxf(sacc[nb][2], sacc[nb][3]));
        }
        t0 = fmaxf(t0, __shfl_xor_sync(0xffffffffu, t0, 1));
        t0 = fmaxf(t0, __shfl_xor_sync(0xffffffffu, t0, 2));
        t1 = fmaxf(t1, __shfl_xor_sync(0xffffffffu, t1, 1));
        t1 = fmaxf(t1, __shfl_xor_sync(0xffffffffu, t1, 2));

        float mn0 = fmaxf(m0v, t0), mn1 = fmaxf(m1v, t1);
        float fac0 = __expf(m0v - mn0), fac1 = __expf(m1v - mn1);
        float rs0 = 0.f, rs1 = 0.f;

        float* prow = Ps + (wq0 + g) * FST + 2 * qd;
        #pragma unroll
        for (int nb = 0; nb < 8; nb++) {
            float p0 = __expf(sacc[nb][0] - mn0);
            float p1 = __expf(sacc[nb][1] - mn0);
            float p2 = __expf(sacc[nb][2] - mn1);
            float p3 = __expf(sacc[nb][3] - mn1);
            rs0 += p0 + p1; rs1 += p2 + p3;
            float2 w0 = { rt32(p0), rt32(p1) };
            float2 w1 = { rt32(p2), rt32(p3) };
            *(float2*)(prow + nb * 8)           = w0;
            *(float2*)(prow + nb * 8 + 8 * FST) = w1;
        }
        rs0 += __shfl_xor_sync(0xffffffffu, rs0, 1);
        rs0 += __shfl_xor_sync(0xffffffffu, rs0, 2);
        rs1 += __shfl_xor_sync(0xffffffffu, rs1, 1);
        rs1 += __shfl_xor_sync(0xffffffffu, rs1, 2);

        l0 = l0 * fac0 + rs0;  l1 = l1 * fac1 + rs1;
        m0v = mn0;  m1v = mn1;
        #pragma unroll
        for (int nb = 0; nb < 8; nb++) {
            oacc[nb][0] *= fac0; oacc[nb][1] *= fac0;
            oacc[nb][2] *= fac1; oacc[nb][3] *= fac1;
        }
        __syncwarp();

        // O += P @ V
        #pragma unroll
        for (int kb = 0; kb < 8; kb++) {
            const float* pa = Ps + (wq0 + g) * FST + kb * 8 + qd;
            uint32_t a0 = __float_as_uint(pa[0]);
            uint32_t a1 = __float_as_uint(pa[8 * FST]);
            uint32_t a2 = __float_as_uint(pa[4]);
            uint32_t a3 = __float_as_uint(pa[8 * FST + 4]);
            #pragma unroll
            for (int nb = 0; nb < 8; nb++) {
                const float* vb = Vs + (kb * 8 + qd) * FST + nb * 8 + g;
                uint32_t b0 = __float_as_uint(vb[0]);
                uint32_t b1 = __float_as_uint(vb[4 * FST]);
                mma_tf32(oacc[nb][0], oacc[nb][1], oacc[nb][2], oacc[nb][3],
                         a0, a1, a2, a3, b0, b1);
            }
        }

        __syncthreads();
        if (more) {
            #pragma unroll
            for (int it = 0; it < 4; it++) {
                int r = r0 + it * 16;
                float* kp = Ks + r * FST + c4;
                kp[0] = rt32(rk[it].x); kp[1] = rt32(rk[it].y);
                kp[2] = rt32(rk[it].z); kp[3] = rt32(rk[it].w);
                float* vp = Vs + r * FST + c4;
                vp[0] = rt32(rv[it].x); vp[1] = rt32(rv[it].y);
                vp[2] = rt32(rv[it].z); vp[3] = rt32(rv[it].w);
            }
            __syncthreads();
        }
    }

    // epilogue: ctx[b, s, h*64 + d]
    const int b = bh >> 4, h = bh & 15;
    const float inv0 = 1.0f / l0, inv1 = 1.0f / l1;
    #pragma unroll
    for (int nb = 0; nb < 8; nb++) {
        const int col = h * DH_ + nb * 8 + 2 * qd;
        float2 o0 = { oacc[nb][0] * inv0, oacc[nb][1] * inv0 };
        float2 o1 = { oacc[nb][2] * inv1, oacc[nb][3] * inv1 };
        *(float2*)(ctx + (size_t)(b * S_ + rowa) * DM_ + col) = o0;
        *(float2*)(ctx + (size_t)(b * S_ + rowb) * DM_ + col) = o1;
    }
}

// ---------------------------------------------------------------------------
extern "C" void kernel_launch(void* const* d_in, const int* in_sizes, int n_in,
                              void* d_out, int out_size)
{
    const float* x      = (const float*)d_in[0];
    const float* qkv_w  = (const float*)d_in[1];
    const float* qkv_b  = (const float*)d_in[2];
    const float* proj_w = (const float*)d_in[3];
    const float* proj_b = (const float*)d_in[4];
    float* out = (float*)d_out;

    float *qkv_s, *q_s, *k_s, *v_s, *ctx_s;
    cudaGetSymbolAddress((void**)&qkv_s, g_qkv);
    cudaGetSymbolAddress((void**)&q_s,   g_q);
    cudaGetSymbolAddress((void**)&k_s,   g_k);
    cudaGetSymbolAddress((void**)&v_s,   g_v);
    cudaGetSymbolAddress((void**)&ctx_s, g_ctx);

    cudaFuncSetAttribute(gemm_tf32, cudaFuncAttributeMaxDynamicSharedMemorySize, GEMM_SMEM);
    cudaFuncSetAttribute(flash_tc,  cudaFuncAttributeMaxDynamicSharedMemorySize, FLASH_SMEM);

    // 1) QKV projection (tf32 mma.sync)
    {
        dim3 grid(3 * DM_ / 128, B_ * S_ / 128);
        gemm_tf32<<<grid, 256, GEMM_SMEM>>>(x, qkv_w, qkv_b, qkv_s, B_ * S_, 3 * DM_, DM_);
    }

    // 2) RoPE + head split
    {
        int total = B_ * S_ * H_ * 32;
        rope_split<<<total / 256, 256>>>(qkv_s);
    }

    // 3) Causal flash attention (tf32 mma.sync)
    {
        dim3 grid(S_ / 128, B_ * H_);
        flash_tc<<<grid, 256, FLASH_SMEM>>>(q_s, k_s, v_s, ctx_s);
    }

    // 4) Output projection (tf32 mma.sync)
    {
        dim3 grid(DM_ / 128, B_ * S_ / 128);
        gemm_tf32<<<grid, 256, GEMM_SMEM>>>(ctx_s, proj_w, proj_b, out, B_ * S_, DM_, DM_);
    }
}

// round 7
// speedup vs baseline: 3.2172x; 1.3522x over previous
#include <cuda_runtime.h>
#include <cstdint>
#include <math.h>

// Problem constants
#define B_  2
#define S_  2048
#define DM_ 1024
#define H_  16
#define DH_ 64

// ---------------- scratch (no allocations allowed; use __device__ globals) --
__device__ float g_qkv[B_ * S_ * 3 * DM_];        // [B*S, 3072]
__device__ float g_q[B_ * H_ * S_ * DH_];          // [BH, S, 64] rope+scale+tf32
__device__ float g_k[B_ * H_ * S_ * DH_];          // rope+tf32
__device__ float g_v[B_ * H_ * S_ * DH_];          // tf32
__device__ float g_ctx[B_ * S_ * DM_];             // [B*S, 1024] tf32, k-permuted
__device__ float g_xr[B_ * S_ * DM_];              // x  tf32, k-permuted
__device__ float g_w1[3 * DM_ * DM_];              // qkv_w tf32, k-permuted
__device__ float g_w2[DM_ * DM_];                  // proj_w tf32, k-permuted

// ---------------------------------------------------------------------------
// helpers (warp-level mma.sync — tcgen05 unavailable on base compute_103)
// ---------------------------------------------------------------------------
__device__ __forceinline__ uint32_t f2tf32(float x) {
    uint32_t r;
    asm("cvt.rna.tf32.f32 %0, %1;" : "=r"(r) : "f"(x));
    return r;
}
__device__ __forceinline__ float rt32(float x) { return __uint_as_float(f2tf32(x)); }

__device__ __forceinline__ void mma_tf32(float& c0, float& c1, float& c2, float& c3,
                                         uint32_t a0, uint32_t a1, uint32_t a2, uint32_t a3,
                                         uint32_t b0, uint32_t b1) {
    asm volatile(
        "mma.sync.aligned.m16n8k8.row.col.f32.tf32.tf32.f32 "
        "{%0,%1,%2,%3}, {%4,%5,%6,%7}, {%8,%9}, {%0,%1,%2,%3};"
        : "+f"(c0), "+f"(c1), "+f"(c2), "+f"(c3)
        : "r"(a0), "r"(a1), "r"(a2), "r"(a3), "r"(b0), "r"(b1));
}

__device__ __forceinline__ uint32_t smem_u32(const void* p) {
    uint32_t a;
    asm("{ .reg .u64 t; cvta.to.shared.u64 t, %1; cvt.u32.u64 %0, t; }" : "=r"(a) : "l"(p));
    return a;
}
__device__ __forceinline__ void cpa16(uint32_t dst, const void* src) {
    asm volatile("cp.async.cg.shared.global [%0], [%1], 16;" :: "r"(dst), "l"(src));
}
#define CP_COMMIT() asm volatile("cp.async.commit_group;" ::: "memory")
#define CP_WAIT1()  asm volatile("cp.async.wait_group 1;" ::: "memory")

// ---------------------------------------------------------------------------
// Prepass: tf32-round + permute k within 8-groups: slot(k) = 2*(k&3)+(k>>2).
// Fragment loads then read orig (k=lc, k=lc+4) as one contiguous float2.
// ---------------------------------------------------------------------------
__global__ void round_perm(const float* __restrict__ src, float* __restrict__ dst, int n8)
{
    int i = blockIdx.x * blockDim.x + threadIdx.x;
    if (i >= n8) return;
    const float4* s = (const float4*)(src + (size_t)i * 8);
    float4 lo = s[0], hi = s[1];            // orig k = 0..3, 4..7
    float4 o0, o1;                          // slots 0..3, 4..7
    o0.x = rt32(lo.x);  o0.z = rt32(lo.y);  // k0->s0, k1->s2
    o1.x = rt32(lo.z);  o1.z = rt32(lo.w);  // k2->s4, k3->s6
    o0.y = rt32(hi.x);  o0.w = rt32(hi.y);  // k4->s1, k5->s3
    o1.y = rt32(hi.z);  o1.w = rt32(hi.w);  // k6->s5, k7->s7
    float4* d = (float4*)(dst + (size_t)i * 8);
    d[0] = o0; d[1] = o1;
}

// ---------------------------------------------------------------------------
// tf32 GEMM: C[M,N] = A[M,K] @ B[N,K]^T + bias[N].
// A,B pre-rounded + k-permuted. 128x128 tile, 8 warps (64x32 each),
// cp.async 3-stage ring, stride-40 smem (conflict-free LDS.64 fragments),
// one __syncthreads per 32-k chunk.
// ---------------------------------------------------------------------------
#define GST  40
#define GSTG (128 * GST)
#define GEMM_SMEM (3 * 2 * GSTG * 4)   // 122880 B

__global__ void __launch_bounds__(256, 1)
gemm_cp(const float* __restrict__ A, const float* __restrict__ Bw,
        const float* __restrict__ bias, float* __restrict__ C,
        int M, int N, int K)
{
    extern __shared__ __align__(16) float sm[];
    const uint32_t smb = smem_u32(sm);
    const int tid = threadIdx.x;
    const int wid = tid >> 5, lane = tid & 31;
    const int wm = (wid >> 2) * 64, wn = (wid & 3) * 32;
    const int lr = lane >> 2, lc = lane & 3;
    const int m0 = blockIdx.y * 128, n0 = blockIdx.x * 128;
    const int NK = K >> 5;
    const int r0 = tid >> 3, c4 = (tid & 7) * 4;

    const float* Ab = A  + (size_t)(m0 + r0) * K + c4;
    const float* Bb = Bw + (size_t)(n0 + r0) * K + c4;

    float acc[4][4][4] = {};

    auto issue = [&](int kc) {
        const int s = kc % 3;
        const uint32_t as = smb + s * 2 * GSTG * 4;
        const uint32_t bs = as + GSTG * 4;
        const int ko = kc * 32;
        #pragma unroll
        for (int it = 0; it < 4; it++) {
            const int r = r0 + it * 32;
            const uint32_t off = (r * GST + c4) * 4;
            cpa16(as + off, Ab + (size_t)(it * 32) * K + ko);
            cpa16(bs + off, Bb + (size_t)(it * 32) * K + ko);
        }
    };

    issue(0); CP_COMMIT();
    issue(1); CP_COMMIT();

    for (int kc = 0; kc < NK; kc++) {
        CP_WAIT1();
        __syncthreads();
        if (kc + 2 < NK) issue(kc + 2);
        CP_COMMIT();

        const float* Ap = sm + (kc % 3) * 2 * GSTG;
        const float* Bp = Ap + GSTG;
        #pragma unroll
        for (int ks = 0; ks < 4; ks++) {
            const int kb = ks * 8;
            uint32_t af[4][4];
            #pragma unroll
            for (int t = 0; t < 4; t++) {
                float2 lo = *(const float2*)(Ap + (wm + t * 16 + lr) * GST + kb + 2 * lc);
                float2 hi = *(const float2*)(Ap + (wm + t * 16 + 8 + lr) * GST + kb + 2 * lc);
                af[t][0] = __float_as_uint(lo.x);
                af[t][1] = __float_as_uint(hi.x);
                af[t][2] = __float_as_uint(lo.y);
                af[t][3] = __float_as_uint(hi.y);
            }
            uint32_t bf[4][2];
            #pragma unroll
            for (int j = 0; j < 4; j++) {
                float2 bb = *(const float2*)(Bp + (wn + j * 8 + lr) * GST + kb + 2 * lc);
                bf[j][0] = __float_as_uint(bb.x);
                bf[j][1] = __float_as_uint(bb.y);
            }
            #pragma unroll
            for (int t = 0; t < 4; t++)
                #pragma unroll
                for (int j = 0; j < 4; j++)
                    mma_tf32(acc[t][j][0], acc[t][j][1], acc[t][j][2], acc[t][j][3],
                             af[t][0], af[t][1], af[t][2], af[t][3],
                             bf[j][0], bf[j][1]);
        }
    }

    #pragma unroll
    for (int t = 0; t < 4; t++) {
        const int row = m0 + wm + t * 16 + lr;
        #pragma unroll
        for (int j = 0; j < 4; j++) {
            const int col = n0 + wn + j * 8 + 2 * lc;
            const float b0 = bias[col], b1 = bias[col + 1];
            float2 o0 = { acc[t][j][0] + b0, acc[t][j][1] + b1 };
            float2 o1 = { acc[t][j][2] + b0, acc[t][j][3] + b1 };
            *(float2*)(C + (size_t)row * N + col)       = o0;
            *(float2*)(C + (size_t)(row + 8) * N + col) = o1;
        }
    }
}

// ---------------------------------------------------------------------------
// RoPE + split heads. Writes q (x0.125, tf32), k (tf32), v (tf32) so flash
// consumes pre-rounded data via raw cp.async copies.
// ---------------------------------------------------------------------------
__global__ void rope_split(const float* __restrict__ qkv)
{
    int idx = blockIdx.x * blockDim.x + threadIdx.x;
    int j = idx & 31;
    int t = idx >> 5;
    int h = t & (H_ - 1); t >>= 4;
    int s = t & (S_ - 1);
    int b = t >> 11;

    const float* src = qkv + (size_t)(b * S_ + s) * (3 * DM_) + h * DH_;

    float inv = expf(-(float)j * 0.287823136624f);   // 10000^(-j/32)
    float ang = (float)s * inv;
    float sn, cs;
    sincosf(ang, &sn, &cs);

    float q1 = src[j],            q2 = src[j + 32];
    float k1 = src[DM_ + j],      k2 = src[DM_ + j + 32];
    float v1 = src[2 * DM_ + j],  v2 = src[2 * DM_ + j + 32];

    size_t dst = ((size_t)(b * H_ + h) * S_ + s) * DH_;
    g_q[dst + j]      = rt32((q1 * cs - q2 * sn) * 0.125f);
    g_q[dst + j + 32] = rt32((q2 * cs + q1 * sn) * 0.125f);
    g_k[dst + j]      = rt32(k1 * cs - k2 * sn);
    g_k[dst + j + 32] = rt32(k2 * cs + k1 * sn);
    g_v[dst + j]      = rt32(v1);
    g_v[dst + j + 32] = rt32(v2);
}

// ---------------------------------------------------------------------------
// Flash attention (tf32 mma.sync, fp32 accum, causal).
// CTA: 128 q-rows x one bh, 8 warps x 16 rows, KV tiles of 64 in a
// cp.async 3-stage ring. Q/K/V pre-rounded. ctx written tf32 + k-permuted
// for the proj GEMM.
// ---------------------------------------------------------------------------
#define FST 68
#define FKV (64 * FST)
#define FLASH_SMEM ((6 * FKV + 128 * FST) * 4)   // 139264 B

__global__ void __launch_bounds__(256, 1)
flash_tc(const float* __restrict__ Qg, const float* __restrict__ Kg,
         const float* __restrict__ Vg, float* __restrict__ ctx)
{
    extern __shared__ __align__(16) float sm[];
    const uint32_t smb = smem_u32(sm);
    float* Ps = sm + 6 * FKV;           // Q staging, then per-warp P slices

    const int tid  = threadIdx.x;
    const int wid  = tid >> 5, lane = tid & 31;
    const int g    = lane >> 2, qd = lane & 3;
    const int wq0  = wid * 16;
    const int bh   = blockIdx.y;
    const int qt   = (gridDim.x - 1) - blockIdx.x;   // longest CTAs first
    const int q0   = qt * 128;

    const float* Qbase = Qg + ((size_t)bh * S_ + q0) * DH_;
    const float* Kbase = Kg + (size_t)bh * S_ * DH_;
    const float* Vbase = Vg + (size_t)bh * S_ * DH_;

    // stage Q (already scaled+rounded) into Ps
    #pragma unroll
    for (int it = 0; it < 8; it++) {
        int idx = tid + it * 256;
        int r = idx >> 4, c = (idx & 15) * 4;
        *(float4*)(Ps + r * FST + c) = *(const float4*)(Qbase + r * DH_ + c);
    }
    __syncthreads();

    uint32_t qf[8][4];
    #pragma unroll
    for (int kb = 0; kb < 8; kb++) {
        const float* b0 = Ps + (wq0 + g) * FST + kb * 8 + qd;
        qf[kb][0] = __float_as_uint(b0[0]);
        qf[kb][1] = __float_as_uint(b0[8 * FST]);
        qf[kb][2] = __float_as_uint(b0[4]);
        qf[kb][3] = __float_as_uint(b0[8 * FST + 4]);
    }
    __syncthreads();

    const int r0 = tid >> 4;             // 0..15
    const int c4 = (tid & 15) * 4;
    auto issueKV = [&](int jt) {
        const int s = jt % 3;
        const uint32_t ks_ = smb + s * 2 * FKV * 4;
        const uint32_t vs_ = ks_ + FKV * 4;
        const float* Kn = Kbase + (size_t)(jt * 64) * DH_;
        const float* Vn = Vbase + (size_t)(jt * 64) * DH_;
        #pragma unroll
        for (int it = 0; it < 4; it++) {
            const int r = r0 + it * 16;
            const uint32_t off = (r * FST + c4) * 4;
            cpa16(ks_ + off, Kn + r * DH_ + c4);
            cpa16(vs_ + off, Vn + r * DH_ + c4);
        }
    };

    const int ntiles = q0 / 64 + 2;
    issueKV(0); CP_COMMIT();
    issueKV(1); CP_COMMIT();

    float m0v = -3.0e38f, m1v = -3.0e38f, l0 = 0.f, l1 = 0.f;
    float oacc[8][4];
    #pragma unroll
    for (int nb = 0; nb < 8; nb++)
        #pragma unroll
        for (int r = 0; r < 4; r++) oacc[nb][r] = 0.f;

    const int rowa = q0 + wq0 + g;
    const int rowb = rowa + 8;

    for (int jt = 0; jt < ntiles; jt++) {
        const int j0 = jt * 64;

        CP_WAIT1();
        __syncthreads();
        if (jt + 2 < ntiles) issueKV(jt + 2);
        CP_COMMIT();

        const float* Ks = sm + (jt % 3) * 2 * FKV;
        const float* Vs = Ks + FKV;

        // S = Q @ K^T (pre-scaled)
        float sacc[8][4];
        #pragma unroll
        for (int nb = 0; nb < 8; nb++)
            #pragma unroll
            for (int r = 0; r < 4; r++) sacc[nb][r] = 0.f;

        #pragma unroll
        for (int kb = 0; kb < 8; kb++) {
            #pragma unroll
            for (int nb = 0; nb < 8; nb++) {
                const float* bp = Ks + (nb * 8 + g) * FST + kb * 8 + qd;
                uint32_t b0 = __float_as_uint(bp[0]);
                uint32_t b1 = __float_as_uint(bp[4]);
                mma_tf32(sacc[nb][0], sacc[nb][1], sacc[nb][2], sacc[nb][3],
                         qf[kb][0], qf[kb][1], qf[kb][2], qf[kb][3], b0, b1);
            }
        }

        // causal mask
        if (j0 + 63 > rowa) {
            #pragma unroll
            for (int nb = 0; nb < 8; nb++) {
                int col = j0 + nb * 8 + 2 * qd;
                if (col     > rowa) sacc[nb][0] = -1.0e30f;
                if (col + 1 > rowa) sacc[nb][1] = -1.0e30f;
                if (col     > rowb) sacc[nb][2] = -1.0e30f;
                if (col + 1 > rowb) sacc[nb][3] = -1.0e30f;
            }
        }

        // online softmax
        float t0 = -3.0e38f, t1 = -3.0e38f;
        #pragma unroll
        for (int nb = 0; nb < 8; nb++) {
            t0 = fmaxf(t0, fmaxf(sacc[nb][0], sacc[nb][1]));
            t1 = fmaxf(t1, fmaxf(sacc[nb][2], sacc[nb][3]));
        }
        t0 = fmaxf(t0, __shfl_xor_sync(0xffffffffu, t0, 1));
        t0 = fmaxf(t0, __shfl_xor_sync(0xffffffffu, t0, 2));
        t1 = fmaxf(t1, __shfl_xor_sync(0xffffffffu, t1, 1));
        t1 = fmaxf(t1, __shfl_xor_sync(0xffffffffu, t1, 2));

        float mn0 = fmaxf(m0v, t0), mn1 = fmaxf(m1v, t1);
        float fac0 = __expf(m0v - mn0), fac1 = __expf(m1v - mn1);
        float rs0 = 0.f, rs1 = 0.f;

        float* prow = Ps + (wq0 + g) * FST + 2 * qd;
        #pragma unroll
        for (int nb = 0; nb < 8; nb++) {
            float p0 = __expf(sacc[nb][0] - mn0);
            float p1 = __expf(sacc[nb][1] - mn0);
            float p2 = __expf(sacc[nb][2] - mn1);
            float p3 = __expf(sacc[nb][3] - mn1);
            rs0 += p0 + p1; rs1 += p2 + p3;
            float2 w0 = { rt32(p0), rt32(p1) };
            float2 w1 = { rt32(p2), rt32(p3) };
            *(float2*)(prow + nb * 8)           = w0;
            *(float2*)(prow + nb * 8 + 8 * FST) = w1;
        }
        rs0 += __shfl_xor_sync(0xffffffffu, rs0, 1);
        rs0 += __shfl_xor_sync(0xffffffffu, rs0, 2);
        rs1 += __shfl_xor_sync(0xffffffffu, rs1, 1);
        rs1 += __shfl_xor_sync(0xffffffffu, rs1, 2);

        l0 = l0 * fac0 + rs0;  l1 = l1 * fac1 + rs1;
        m0v = mn0;  m1v = mn1;
        #pragma unroll
        for (int nb = 0; nb < 8; nb++) {
            oacc[nb][0] *= fac0; oacc[nb][1] *= fac0;
            oacc[nb][2] *= fac1; oacc[nb][3] *= fac1;
        }
        __syncwarp();

        // O += P @ V
        #pragma unroll
        for (int kb = 0; kb < 8; kb++) {
            const float* pa = Ps + (wq0 + g) * FST + kb * 8 + qd;
            uint32_t a0 = __float_as_uint(pa[0]);
            uint32_t a1 = __float_as_uint(pa[8 * FST]);
            uint32_t a2 = __float_as_uint(pa[4]);
            uint32_t a3 = __float_as_uint(pa[8 * FST + 4]);
            #pragma unroll
            for (int nb = 0; nb < 8; nb++) {
                const float* vb = Vs + (kb * 8 + qd) * FST + nb * 8 + g;
                uint32_t b0 = __float_as_uint(vb[0]);
                uint32_t b1 = __float_as_uint(vb[4 * FST]);
                mma_tf32(oacc[nb][0], oacc[nb][1], oacc[nb][2], oacc[nb][3],
                         a0, a1, a2, a3, b0, b1);
            }
        }
    }

    // epilogue: ctx[b, s, perm(h*64+d)] tf32-rounded + k-permuted for proj GEMM
    const int b = bh >> 4, h = bh & 15;
    const float inv0 = 1.0f / l0, inv1 = 1.0f / l1;
    // slots within the 8-group for cols 2qd, 2qd+1:
    const int s0 = (qd < 2) ? 4 * qd     : 4 * qd - 7;
    const int s1 = (qd < 2) ? 4 * qd + 2 : 4 * qd - 5;
    #pragma unroll
    for (int nb = 0; nb < 8; nb++) {
        float* pa = ctx + (size_t)(b * S_ + rowa) * DM_ + h * DH_ + nb * 8;
        float* pb = ctx + (size_t)(b * S_ + rowb) * DM_ + h * DH_ + nb * 8;
        pa[s0] = rt32(oacc[nb][0] * inv0);
        pa[s1] = rt32(oacc[nb][1] * inv0);
        pb[s0] = rt32(oacc[nb][2] * inv1);
        pb[s1] = rt32(oacc[nb][3] * inv1);
    }
}

// ---------------------------------------------------------------------------
extern "C" void kernel_launch(void* const* d_in, const int* in_sizes, int n_in,
                              void* d_out, int out_size)
{
    const float* x      = (const float*)d_in[0];
    const float* qkv_w  = (const float*)d_in[1];
    const float* qkv_b  = (const float*)d_in[2];
    const float* proj_w = (const float*)d_in[3];
    const float* proj_b = (const float*)d_in[4];
    float* out = (float*)d_out;

    float *qkv_s, *q_s, *k_s, *v_s, *ctx_s, *xr_s, *w1_s, *w2_s;
    cudaGetSymbolAddress((void**)&qkv_s, g_qkv);
    cudaGetSymbolAddress((void**)&q_s,   g_q);
    cudaGetSymbolAddress((void**)&k_s,   g_k);
    cudaGetSymbolAddress((void**)&v_s,   g_v);
    cudaGetSymbolAddress((void**)&ctx_s, g_ctx);
    cudaGetSymbolAddress((void**)&xr_s,  g_xr);
    cudaGetSymbolAddress((void**)&w1_s,  g_w1);
    cudaGetSymbolAddress((void**)&w2_s,  g_w2);

    cudaFuncSetAttribute(gemm_cp,  cudaFuncAttributeMaxDynamicSharedMemorySize, GEMM_SMEM);
    cudaFuncSetAttribute(flash_tc, cudaFuncAttributeMaxDynamicSharedMemorySize, FLASH_SMEM);

    // 0) pre-round (tf32) + k-permute GEMM operands
    round_perm<<<(B_ * S_ * DM_ / 8 + 255) / 256, 256>>>(x, xr_s, B_ * S_ * DM_ / 8);
    round_perm<<<(3 * DM_ * DM_ / 8 + 255) / 256, 256>>>(qkv_w, w1_s, 3 * DM_ * DM_ / 8);
    round_perm<<<(DM_ * DM_ / 8 + 255) / 256, 256>>>(proj_w, w2_s, DM_ * DM_ / 8);

    // 1) QKV projection
    {
        dim3 grid(3 * DM_ / 128, B_ * S_ / 128);
        gemm_cp<<<grid, 256, GEMM_SMEM>>>(xr_s, w1_s, qkv_b, qkv_s, B_ * S_, 3 * DM_, DM_);
    }

    // 2) RoPE + head split (pre-rounds q/k/v for flash)
    {
        int total = B_ * S_ * H_ * 32;
        rope_split<<<total / 256, 256>>>(qkv_s);
    }

    // 3) Causal flash attention
    {
        dim3 grid(S_ / 128, B_ * H_);
        flash_tc<<<grid, 256, FLASH_SMEM>>>(q_s, k_s, v_s, ctx_s);
    }

    // 4) Output projection
    {
        dim3 grid(DM_ / 128, B_ * S_ / 128);
        gemm_cp<<<grid, 256, GEMM_SMEM>>>(ctx_s, w2_s, proj_b, out, B_ * S_, DM_, DM_);
    }
}

// round 8
// speedup vs baseline: 3.4116x; 1.0604x over previous
#include <cuda_runtime.h>
#include <cstdint>
#include <math.h>

// Problem constants
#define B_  2
#define S_  2048
#define DM_ 1024
#define H_  16
#define DH_ 64

// ---------------- scratch (no allocations allowed; use __device__ globals) --
__device__ float g_qkv[B_ * S_ * 3 * DM_];        // [B*S, 3072]
__device__ float g_q[B_ * H_ * S_ * DH_];          // [BH, S, 64] rope+scale+tf32
__device__ float g_k[B_ * H_ * S_ * DH_];          // rope+tf32
__device__ float g_v[B_ * H_ * S_ * DH_];          // tf32
__device__ float g_ctx[B_ * S_ * DM_];             // [B*S, 1024] tf32, k-permuted
__device__ float g_xr[B_ * S_ * DM_];              // x  tf32, k-permuted
__device__ float g_w1[3 * DM_ * DM_];              // qkv_w tf32, k-permuted
__device__ float g_w2[DM_ * DM_];                  // proj_w tf32, k-permuted

// ---------------------------------------------------------------------------
// helpers (warp-level mma.sync — tcgen05 unavailable on base compute_103)
// ---------------------------------------------------------------------------
__device__ __forceinline__ uint32_t f2tf32(float x) {
    uint32_t r;
    asm("cvt.rna.tf32.f32 %0, %1;" : "=r"(r) : "f"(x));
    return r;
}
__device__ __forceinline__ float rt32(float x) { return __uint_as_float(f2tf32(x)); }

__device__ __forceinline__ void mma_tf32(float& c0, float& c1, float& c2, float& c3,
                                         uint32_t a0, uint32_t a1, uint32_t a2, uint32_t a3,
                                         uint32_t b0, uint32_t b1) {
    asm volatile(
        "mma.sync.aligned.m16n8k8.row.col.f32.tf32.tf32.f32 "
        "{%0,%1,%2,%3}, {%4,%5,%6,%7}, {%8,%9}, {%0,%1,%2,%3};"
        : "+f"(c0), "+f"(c1), "+f"(c2), "+f"(c3)
        : "r"(a0), "r"(a1), "r"(a2), "r"(a3), "r"(b0), "r"(b1));
}

__device__ __forceinline__ uint32_t smem_u32(const void* p) {
    uint32_t a;
    asm("{ .reg .u64 t; cvta.to.shared.u64 t, %1; cvt.u32.u64 %0, t; }" : "=r"(a) : "l"(p));
    return a;
}
__device__ __forceinline__ void cpa16(uint32_t dst, const void* src) {
    asm volatile("cp.async.cg.shared.global [%0], [%1], 16;" :: "r"(dst), "l"(src));
}
#define CP_COMMIT() asm volatile("cp.async.commit_group;" ::: "memory")
#define CP_WAIT1()  asm volatile("cp.async.wait_group 1;" ::: "memory")

// ---------------------------------------------------------------------------
// Prepass: tf32-round + permute k within 8-groups: slot(k) = 2*(k&3)+(k>>2).
// ---------------------------------------------------------------------------
__global__ void round_perm(const float* __restrict__ src, float* __restrict__ dst, int n8)
{
    int i = blockIdx.x * blockDim.x + threadIdx.x;
    if (i >= n8) return;
    const float4* s = (const float4*)(src + (size_t)i * 8);
    float4 lo = s[0], hi = s[1];
    float4 o0, o1;
    o0.x = rt32(lo.x);  o0.z = rt32(lo.y);
    o1.x = rt32(lo.z);  o1.z = rt32(lo.w);
    o0.y = rt32(hi.x);  o0.w = rt32(hi.y);
    o1.y = rt32(hi.z);  o1.w = rt32(hi.w);
    float4* d = (float4*)(dst + (size_t)i * 8);
    d[0] = o0; d[1] = o1;
}

// ---------------------------------------------------------------------------
// tf32 GEMM: C[M,N] = A[M,K] @ B[N,K]^T + bias[N].
// A,B pre-rounded + k-permuted. 128x128 tile, 8 warps (64x32 each),
// cp.async 2-stage ring (80KB smem -> 2 CTAs/SM), <=128 regs.
// ---------------------------------------------------------------------------
#define GST  40
#define GSTG (128 * GST)
#define GEMM_SMEM (2 * 2 * GSTG * 4)   // 81920 B

__global__ void __launch_bounds__(256, 2)
gemm_cp(const float* __restrict__ A, const float* __restrict__ Bw,
        const float* __restrict__ bias, float* __restrict__ C,
        int M, int N, int K)
{
    extern __shared__ __align__(16) float sm[];
    const uint32_t smb = smem_u32(sm);
    const int tid = threadIdx.x;
    const int wid = tid >> 5, lane = tid & 31;
    const int wm = (wid >> 2) * 64, wn = (wid & 3) * 32;
    const int lr = lane >> 2, lc = lane & 3;
    const int m0 = blockIdx.y * 128, n0 = blockIdx.x * 128;
    const int NK = K >> 5;
    const int r0 = tid >> 3, c4 = (tid & 7) * 4;

    const float* Ab = A  + (size_t)(m0 + r0) * K + c4;
    const float* Bb = Bw + (size_t)(n0 + r0) * K + c4;

    float acc[4][4][4] = {};

    auto issue = [&](int kc) {
        const int s = kc & 1;
        const uint32_t as = smb + s * 2 * GSTG * 4;
        const uint32_t bs = as + GSTG * 4;
        const int ko = kc * 32;
        #pragma unroll
        for (int it = 0; it < 4; it++) {
            const int r = r0 + it * 32;
            const uint32_t off = (r * GST + c4) * 4;
            cpa16(as + off, Ab + (size_t)(it * 32) * K + ko);
            cpa16(bs + off, Bb + (size_t)(it * 32) * K + ko);
        }
    };

    issue(0); CP_COMMIT();

    for (int kc = 0; kc < NK; kc++) {
        if (kc + 1 < NK) issue(kc + 1);
        CP_COMMIT();
        CP_WAIT1();
        __syncthreads();                       // chunk kc visible to all warps

        const float* Ap = sm + (kc & 1) * 2 * GSTG;
        const float* Bp = Ap + GSTG;
        #pragma unroll
        for (int ks = 0; ks < 4; ks++) {
            const int kb = ks * 8;
            uint32_t af[4][4];
            #pragma unroll
            for (int t = 0; t < 4; t++) {
                float2 lo = *(const float2*)(Ap + (wm + t * 16 + lr) * GST + kb + 2 * lc);
                float2 hi = *(const float2*)(Ap + (wm + t * 16 + 8 + lr) * GST + kb + 2 * lc);
                af[t][0] = __float_as_uint(lo.x);
                af[t][1] = __float_as_uint(hi.x);
                af[t][2] = __float_as_uint(lo.y);
                af[t][3] = __float_as_uint(hi.y);
            }
            uint32_t bf[4][2];
            #pragma unroll
            for (int j = 0; j < 4; j++) {
                float2 bb = *(const float2*)(Bp + (wn + j * 8 + lr) * GST + kb + 2 * lc);
                bf[j][0] = __float_as_uint(bb.x);
                bf[j][1] = __float_as_uint(bb.y);
            }
            #pragma unroll
            for (int t = 0; t < 4; t++)
                #pragma unroll
                for (int j = 0; j < 4; j++)
                    mma_tf32(acc[t][j][0], acc[t][j][1], acc[t][j][2], acc[t][j][3],
                             af[t][0], af[t][1], af[t][2], af[t][3],
                             bf[j][0], bf[j][1]);
        }
        __syncthreads();                       // buf kc&1 free for issue(kc+2)
    }

    #pragma unroll
    for (int t = 0; t < 4; t++) {
        const int row = m0 + wm + t * 16 + lr;
        #pragma unroll
        for (int j = 0; j < 4; j++) {
            const int col = n0 + wn + j * 8 + 2 * lc;
            const float b0 = bias[col], b1 = bias[col + 1];
            float2 o0 = { acc[t][j][0] + b0, acc[t][j][1] + b1 };
            float2 o1 = { acc[t][j][2] + b0, acc[t][j][3] + b1 };
            *(float2*)(C + (size_t)row * N + col)       = o0;
            *(float2*)(C + (size_t)(row + 8) * N + col) = o1;
        }
    }
}

// ---------------------------------------------------------------------------
// RoPE + split heads. Writes q (x0.125, tf32), k (tf32), v (tf32).
// ---------------------------------------------------------------------------
__global__ void rope_split(const float* __restrict__ qkv)
{
    int idx = blockIdx.x * blockDim.x + threadIdx.x;
    int j = idx & 31;
    int t = idx >> 5;
    int h = t & (H_ - 1); t >>= 4;
    int s = t & (S_ - 1);
    int b = t >> 11;

    const float* src = qkv + (size_t)(b * S_ + s) * (3 * DM_) + h * DH_;

    float inv = expf(-(float)j * 0.287823136624f);
    float ang = (float)s * inv;
    float sn, cs;
    sincosf(ang, &sn, &cs);

    float q1 = src[j],            q2 = src[j + 32];
    float k1 = src[DM_ + j],      k2 = src[DM_ + j + 32];
    float v1 = src[2 * DM_ + j],  v2 = src[2 * DM_ + j + 32];

    size_t dst = ((size_t)(b * H_ + h) * S_ + s) * DH_;
    g_q[dst + j]      = rt32((q1 * cs - q2 * sn) * 0.125f);
    g_q[dst + j + 32] = rt32((q2 * cs + q1 * sn) * 0.125f);
    g_k[dst + j]      = rt32(k1 * cs - k2 * sn);
    g_k[dst + j + 32] = rt32(k2 * cs + k1 * sn);
    g_v[dst + j]      = rt32(v1);
    g_v[dst + j + 32] = rt32(v2);
}

// ---------------------------------------------------------------------------
// Flash attention (tf32 mma.sync, fp32 accum, causal) — unchanged from R7.
// ---------------------------------------------------------------------------
#define FST 68
#define FKV (64 * FST)
#define FLASH_SMEM ((6 * FKV + 128 * FST) * 4)   // 139264 B

__global__ void __launch_bounds__(256, 1)
flash_tc(const float* __restrict__ Qg, const float* __restrict__ Kg,
         const float* __restrict__ Vg, float* __restrict__ ctx)
{
    extern __shared__ __align__(16) float sm[];
    const uint32_t smb = smem_u32(sm);
    float* Ps = sm + 6 * FKV;

    const int tid  = threadIdx.x;
    const int wid  = tid >> 5, lane = tid & 31;
    const int g    = lane >> 2, qd = lane & 3;
    const int wq0  = wid * 16;
    const int bh   = blockIdx.y;
    const int qt   = (gridDim.x - 1) - blockIdx.x;
    const int q0   = qt * 128;

    const float* Qbase = Qg + ((size_t)bh * S_ + q0) * DH_;
    const float* Kbase = Kg + (size_t)bh * S_ * DH_;
    const float* Vbase = Vg + (size_t)bh * S_ * DH_;

    #pragma unroll
    for (int it = 0; it < 8; it++) {
        int idx = tid + it * 256;
        int r = idx >> 4, c = (idx & 15) * 4;
        *(float4*)(Ps + r * FST + c) = *(const float4*)(Qbase + r * DH_ + c);
    }
    __syncthreads();

    uint32_t qf[8][4];
    #pragma unroll
    for (int kb = 0; kb < 8; kb++) {
        const float* b0 = Ps + (wq0 + g) * FST + kb * 8 + qd;
        qf[kb][0] = __float_as_uint(b0[0]);
        qf[kb][1] = __float_as_uint(b0[8 * FST]);
        qf[kb][2] = __float_as_uint(b0[4]);
        qf[kb][3] = __float_as_uint(b0[8 * FST + 4]);
    }
    __syncthreads();

    const int r0 = tid >> 4;
    const int c4 = (tid & 15) * 4;
    auto issueKV = [&](int jt) {
        const int s = jt % 3;
        const uint32_t ks_ = smb + s * 2 * FKV * 4;
        const uint32_t vs_ = ks_ + FKV * 4;
        const float* Kn = Kbase + (size_t)(jt * 64) * DH_;
        const float* Vn = Vbase + (size_t)(jt * 64) * DH_;
        #pragma unroll
        for (int it = 0; it < 4; it++) {
            const int r = r0 + it * 16;
            const uint32_t off = (r * FST + c4) * 4;
            cpa16(ks_ + off, Kn + r * DH_ + c4);
            cpa16(vs_ + off, Vn + r * DH_ + c4);
        }
    };

    const int ntiles = q0 / 64 + 2;
    issueKV(0); CP_COMMIT();
    issueKV(1); CP_COMMIT();

    float m0v = -3.0e38f, m1v = -3.0e38f, l0 = 0.f, l1 = 0.f;
    float oacc[8][4];
    #pragma unroll
    for (int nb = 0; nb < 8; nb++)
        #pragma unroll
        for (int r = 0; r < 4; r++) oacc[nb][r] = 0.f;

    const int rowa = q0 + wq0 + g;
    const int rowb = rowa + 8;

    for (int jt = 0; jt < ntiles; jt++) {
        const int j0 = jt * 64;

        CP_WAIT1();
        __syncthreads();
        if (jt + 2 < ntiles) issueKV(jt + 2);
        CP_COMMIT();

        const float* Ks = sm + (jt % 3) * 2 * FKV;
        const float* Vs = Ks + FKV;

        float sacc[8][4];
        #pragma unroll
        for (int nb = 0; nb < 8; nb++)
            #pragma unroll
            for (int r = 0; r < 4; r++) sacc[nb][r] = 0.f;

        #pragma unroll
        for (int kb = 0; kb < 8; kb++) {
            #pragma unroll
            for (int nb = 0; nb < 8; nb++) {
                const float* bp = Ks + (nb * 8 + g) * FST + kb * 8 + qd;
                uint32_t b0 = __float_as_uint(bp[0]);
                uint32_t b1 = __float_as_uint(bp[4]);
                mma_tf32(sacc[nb][0], sacc[nb][1], sacc[nb][2], sacc[nb][3],
                         qf[kb][0], qf[kb][1], qf[kb][2], qf[kb][3], b0, b1);
            }
        }

        if (j0 + 63 > rowa) {
            #pragma unroll
            for (int nb = 0; nb < 8; nb++) {
                int col = j0 + nb * 8 + 2 * qd;
                if (col     > rowa) sacc[nb][0] = -1.0e30f;
                if (col + 1 > rowa) sacc[nb][1] = -1.0e30f;
                if (col     > rowb) sacc[nb][2] = -1.0e30f;
                if (col + 1 > rowb) sacc[nb][3] = -1.0e30f;
            }
        }

        float t0 = -3.0e38f, t1 = -3.0e38f;
        #pragma unroll
        for (int nb = 0; nb < 8; nb++) {
            t0 = fmaxf(t0, fmaxf(sacc[nb][0], sacc[nb][1]));
            t1 = fmaxf(t1, fmaxf(sacc[nb][2], sacc[nb][3]));
        }
        t0 = fmaxf(t0, __shfl_xor_sync(0xffffffffu, t0, 1));
        t0 = fmaxf(t0, __shfl_xor_sync(0xffffffffu, t0, 2));
        t1 = fmaxf(t1, __shfl_xor_sync(0xffffffffu, t1, 1));
        t1 = fmaxf(t1, __shfl_xor_sync(0xffffffffu, t1, 2));

        float mn0 = fmaxf(m0v, t0), mn1 = fmaxf(m1v, t1);
        float fac0 = __expf(m0v - mn0), fac1 = __expf(m1v - mn1);
        float rs0 = 0.f, rs1 = 0.f;

        float* prow = Ps + (wq0 + g) * FST + 2 * qd;
        #pragma unroll
        for (int nb = 0; nb < 8; nb++) {
            float p0 = __expf(sacc[nb][0] - mn0);
            float p1 = __expf(sacc[nb][1] - mn0);
            float p2 = __expf(sacc[nb][2] - mn1);
            float p3 = __expf(sacc[nb][3] - mn1);
            rs0 += p0 + p1; rs1 += p2 + p3;
            float2 w0 = { rt32(p0), rt32(p1) };
            float2 w1 = { rt32(p2), rt32(p3) };
            *(float2*)(prow + nb * 8)           = w0;
            *(float2*)(prow + nb * 8 + 8 * FST) = w1;
        }
        rs0 += __shfl_xor_sync(0xffffffffu, rs0, 1);
        rs0 += __shfl_xor_sync(0xffffffffu, rs0, 2);
        rs1 += __shfl_xor_sync(0xffffffffu, rs1, 1);
        rs1 += __shfl_xor_sync(0xffffffffu, rs1, 2);

        l0 = l0 * fac0 + rs0;  l1 = l1 * fac1 + rs1;
        m0v = mn0;  m1v = mn1;
        #pragma unroll
        for (int nb = 0; nb < 8; nb++) {
            oacc[nb][0] *= fac0; oacc[nb][1] *= fac0;
            oacc[nb][2] *= fac1; oacc[nb][3] *= fac1;
        }
        __syncwarp();

        #pragma unroll
        for (int kb = 0; kb < 8; kb++) {
            const float* pa = Ps + (wq0 + g) * FST + kb * 8 + qd;
            uint32_t a0 = __float_as_uint(pa[0]);
            uint32_t a1 = __float_as_uint(pa[8 * FST]);
            uint32_t a2 = __float_as_uint(pa[4]);
            uint32_t a3 = __float_as_uint(pa[8 * FST + 4]);
            #pragma unroll
            for (int nb = 0; nb < 8; nb++) {
                const float* vb = Vs + (kb * 8 + qd) * FST + nb * 8 + g;
                uint32_t b0 = __float_as_uint(vb[0]);
                uint32_t b1 = __float_as_uint(vb[4 * FST]);
                mma_tf32(oacc[nb][0], oacc[nb][1], oacc[nb][2], oacc[nb][3],
                         a0, a1, a2, a3, b0, b1);
            }
        }
    }

    const int b = bh >> 4, h = bh & 15;
    const float inv0 = 1.0f / l0, inv1 = 1.0f / l1;
    const int s0 = (qd < 2) ? 4 * qd     : 4 * qd - 7;
    const int s1 = (qd < 2) ? 4 * qd + 2 : 4 * qd - 5;
    #pragma unroll
    for (int nb = 0; nb < 8; nb++) {
        float* pa = ctx + (size_t)(b * S_ + rowa) * DM_ + h * DH_ + nb * 8;
        float* pb = ctx + (size_t)(b * S_ + rowb) * DM_ + h * DH_ + nb * 8;
        pa[s0] = rt32(oacc[nb][0] * inv0);
        pa[s1] = rt32(oacc[nb][1] * inv0);
        pb[s0] = rt32(oacc[nb][2] * inv1);
        pb[s1] = rt32(oacc[nb][3] * inv1);
    }
}

// ---------------------------------------------------------------------------
extern "C" void kernel_launch(void* const* d_in, const int* in_sizes, int n_in,
                              void* d_out, int out_size)
{
    const float* x      = (const float*)d_in[0];
    const float* qkv_w  = (const float*)d_in[1];
    const float* qkv_b  = (const float*)d_in[2];
    const float* proj_w = (const float*)d_in[3];
    const float* proj_b = (const float*)d_in[4];
    float* out = (float*)d_out;

    float *qkv_s, *q_s, *k_s, *v_s, *ctx_s, *xr_s, *w1_s, *w2_s;
    cudaGetSymbolAddress((void**)&qkv_s, g_qkv);
    cudaGetSymbolAddress((void**)&q_s,   g_q);
    cudaGetSymbolAddress((void**)&k_s,   g_k);
    cudaGetSymbolAddress((void**)&v_s,   g_v);
    cudaGetSymbolAddress((void**)&ctx_s, g_ctx);
    cudaGetSymbolAddress((void**)&xr_s,  g_xr);
    cudaGetSymbolAddress((void**)&w1_s,  g_w1);
    cudaGetSymbolAddress((void**)&w2_s,  g_w2);

    cudaFuncSetAttribute(gemm_cp,  cudaFuncAttributeMaxDynamicSharedMemorySize, GEMM_SMEM);
    cudaFuncSetAttribute(flash_tc, cudaFuncAttributeMaxDynamicSharedMemorySize, FLASH_SMEM);

    // 0) pre-round (tf32) + k-permute GEMM operands
    round_perm<<<(B_ * S_ * DM_ / 8 + 255) / 256, 256>>>(x, xr_s, B_ * S_ * DM_ / 8);
    round_perm<<<(3 * DM_ * DM_ / 8 + 255) / 256, 256>>>(qkv_w, w1_s, 3 * DM_ * DM_ / 8);
    round_perm<<<(DM_ * DM_ / 8 + 255) / 256, 256>>>(proj_w, w2_s, DM_ * DM_ / 8);

    // 1) QKV projection
    {
        dim3 grid(3 * DM_ / 128, B_ * S_ / 128);
        gemm_cp<<<grid, 256, GEMM_SMEM>>>(xr_s, w1_s, qkv_b, qkv_s, B_ * S_, 3 * DM_, DM_);
    }

    // 2) RoPE + head split
    {
        int total = B_ * S_ * H_ * 32;
        rope_split<<<total / 256, 256>>>(qkv_s);
    }

    // 3) Causal flash attention
    {
        dim3 grid(S_ / 128, B_ * H_);
        flash_tc<<<grid, 256, FLASH_SMEM>>>(q_s, k_s, v_s, ctx_s);
    }

    // 4) Output projection
    {
        dim3 grid(DM_ / 128, B_ * S_ / 128);
        gemm_cp<<<grid, 256, GEMM_SMEM>>>(ctx_s, w2_s, proj_b, out, B_ * S_, DM_, DM_);
    }
}